// round 17
// baseline (speedup 1.0000x reference)
#include <cuda_runtime.h>
#include <math.h>

#define W 4096
#define S4 1024           // float4 per row
#define NKMAX 1024
#define SHARP 50.0f
#define MAXWIN 64
#define CGRID 1024        // corr blocks (subset of k_fused's grid)
                          // CK = 1 key per corr block

// ---------------- device scratch (no allocations allowed) ----------------
// All counters are MONOTONIC across graph replays (no reset kernel needed).
__device__ float2 g_mix[W];       // noisy_mix
__device__ float2 g_tw[W];        // twiddle table e^{i 2pi m / W}
__device__ float  g_corr[NKMAX];
__device__ unsigned g_cd;         // corr-blocks-done counter (election)
__device__ unsigned g_t3;         // k_fused entry ticket (replay index)
__device__ unsigned g_done;       // softmax-done epoch
__device__ int    g_nwin;         // number of nonzero-attention winners
__device__ int    g_winn[MAXWIN]; // winner key indices (sorted ascending)
__device__ float  g_wina[MAXWIN]; // winner attention weights

// block-wide complex reduction (256 threads, 8 warps). Caller syncs before reuse.
__device__ __forceinline__ float2 block_reduce_c(float re, float im, float2* sred) {
#pragma unroll
    for (int off = 16; off; off >>= 1) {
        re += __shfl_xor_sync(0xffffffffu, re, off);
        im += __shfl_xor_sync(0xffffffffu, im, off);
    }
    int wid = threadIdx.x >> 5;
    if ((threadIdx.x & 31) == 0) sred[wid] = make_float2(re, im);
    __syncthreads();
    float2 acc = sred[0];
#pragma unroll
    for (int i = 1; i < 8; i++) { acc.x += sred[i].x; acc.y += sred[i].y; }
    return acc;
}

__device__ __forceinline__ void l2_prefetch(const void* p) {
    asm volatile("prefetch.global.L2 [%0];" :: "l"(p));
}

// ---------------- phase 1: noisy_mix[w] = sum_s holo*conj(cue) ----------------
// Pure R12 form: nothing overlaps this 81%-DRAM kernel.
__global__ __launch_bounds__(256) void k_mix(
    const float4* __restrict__ hr, const float4* __restrict__ hi,
    const float4* __restrict__ cr, const float4* __restrict__ ci)
{
    int row = blockIdx.x;
    int t   = threadIdx.x;
    if (row < 16) {   // side job: twiddle table
        int i = row * 256 + t;
        float s, c;
        sincospif((float)i * (1.0f / 2048.0f), &s, &c);  // i/2048 exact in fp32
        g_tw[i] = make_float2(c, s);
    }
    int base = row * S4;
    float re = 0.f, im = 0.f;
#pragma unroll
    for (int k = 0; k < 4; k++) {
        int i = base + t + k * 256;
        float4 a = hr[i];            // retain in L2 for k_fused
        float4 b = hi[i];
        float4 c = __ldcs(&cr[i]);   // streaming
        float4 d = __ldcs(&ci[i]);
        re += a.x * c.x + b.x * d.x;  im += b.x * c.x - a.x * d.x;
        re += a.y * c.y + b.y * d.y;  im += b.y * c.y - a.y * d.y;
        re += a.z * c.z + b.z * d.z;  im += b.z * c.z - a.z * d.z;
        re += a.w * c.w + b.w * d.w;  im += b.w * c.w - a.w * d.w;
    }
    __shared__ float2 sred[8];
    float2 acc = block_reduce_c(re, im, sred);
    if (t == 0) g_mix[row] = acc;
}

// ====== phase 2+3 fused: corr (blocks 0..1023, 1 key each) + softmax + out ===
// Max occupancy (8 blocks/SM, 32 regs); rows warmed via zero-register
// L2 prefetch that overlaps the corr/softmax critical section.
__global__ __launch_bounds__(256, 8) void k_fused(
    const float4* __restrict__ hr, const float4* __restrict__ hi,
    float4* __restrict__ out, const int* __restrict__ nkp)
{
    int t   = threadIdx.x;
    int bid = blockIdx.x;
    int row = (W - 1) - bid;          // reverse: hit L2-hot tail of k_mix
    int i0  = row * S4 + t;
    __shared__ float2 sred[8];

    // replay index (monotonic ticket)
    __shared__ unsigned sR;
    if (t == 0) sR = atomicAdd(&g_t3, 1u) >> 12;   // / 4096 blocks per launch
    __syncthreads();
    unsigned rep = sR;

    // L2 prefetch of this block's row — only if the epoch isn't published yet
    // (wave-1 blocks overlap corr; later waves skip).
    if (*(volatile unsigned*)&g_done <= rep) {
#pragma unroll
        for (int k = 0; k < 4; k++) {
            l2_prefetch(&hr[i0 + k * 256]);
            l2_prefetch(&hi[i0 + k * 256]);
        }
    }

    int nk = *nkp;

    if (bid < CGRID) {
        // ---- correlation for key n=bid via register phasor recurrence ----
        // twiddle at w advances by rot = e^{i 2pi f*256/W} per 256-step chunk
        unsigned f = (unsigned)bid + 1u;
        float2 t0 = g_tw[(f * (unsigned)t) & 4095u];   // exact init
        float2 r0 = g_tw[(f << 8) & 4095u];            // exact rotation
        float tre = t0.x, tim = t0.y;
        float are = 0.f, aim = 0.f;
#pragma unroll
        for (int ch = 0; ch < 16; ch++) {
            float2 m = __ldg(&g_mix[t + 256 * ch]);
            are += tre * m.x - tim * m.y;
            aim += tre * m.y + tim * m.x;
            float nr = tre * r0.x - tim * r0.y;
            tim      = tre * r0.y + tim * r0.x;
            tre      = nr;
        }
        float2 acc = block_reduce_c(are, aim, sred);
        if (t == 0 && bid < nk) g_corr[bid] = sqrtf(acc.x * acc.x + acc.y * acc.y);
        __syncthreads();
        __threadfence();

        // election: the CGRID-th finisher of this replay does the softmax
        __shared__ unsigned sT;
        if (t == 0) sT = atomicAdd(&g_cd, 1u);
        __syncthreads();
        if ((sT & (CGRID - 1u)) == (CGRID - 1u)) {
            __threadfence();
            __shared__ float sredf[8];
            __shared__ float slog[NKMAX];
            __shared__ int   s_cnt;
            if (t == 0) s_cnt = 0;

            float l[4], mx = -INFINITY;
#pragma unroll
            for (int j = 0; j < 4; j++) {
                int n = t + 256 * j;
                float c = (n < nk) ? __ldcg(&g_corr[n]) : 0.f;
                l[j] = (n < nk) ? c * SHARP : -INFINITY;
                mx = fmaxf(mx, l[j]);
            }
#pragma unroll
            for (int off = 16; off; off >>= 1) mx = fmaxf(mx, __shfl_xor_sync(0xffffffffu, mx, off));
            if ((t & 31) == 0) sredf[t >> 5] = mx;
            __syncthreads();
            float bm = sredf[0];
#pragma unroll
            for (int i = 1; i < 8; i++) bm = fmaxf(bm, sredf[i]);
            __syncthreads();

            float e[4], s = 0.f;
#pragma unroll
            for (int j = 0; j < 4; j++) {
                int n = t + 256 * j;
                e[j] = (n < nk) ? expf(l[j] - bm) : 0.f;
                slog[t + 256 * j] = e[j];
                s += e[j];
            }
#pragma unroll
            for (int off = 16; off; off >>= 1) s += __shfl_xor_sync(0xffffffffu, s, off);
            if ((t & 31) == 0) sredf[t >> 5] = s;
            __syncthreads();
            float bs = sredf[0];
#pragma unroll
            for (int i = 1; i < 8; i++) bs += sredf[i];
            __syncthreads();

#pragma unroll
            for (int j = 0; j < 4; j++) {
                int n = t + 256 * j;
                float a = slog[n] / bs;
                if (a != 0.f && n < nk) {
                    int slot = atomicAdd(&s_cnt, 1);
                    if (slot < MAXWIN) { g_winn[slot] = n; g_wina[slot] = a; }
                }
            }
            __syncthreads();
            if (t == 0) {
                int m = s_cnt < MAXWIN ? s_cnt : MAXWIN;
                for (int i = 1; i < m; i++) {      // sort ascending by n
                    int   kn = g_winn[i];
                    float ka = g_wina[i];
                    int j = i - 1;
                    while (j >= 0 && g_winn[j] > kn) {
                        g_winn[j + 1] = g_winn[j]; g_wina[j + 1] = g_wina[j]; j--;
                    }
                    g_winn[j + 1] = kn; g_wina[j + 1] = ka;
                }
                g_nwin = m;
                __threadfence();
                atomicAdd(&g_done, 1u);            // publish epoch
            }
        }
    }

    // ---- wait for this replay's softmax epoch ----
    if (t == 0) {
        volatile unsigned* p = &g_done;
        while (*p <= rep) __nanosleep(64);
    }
    __syncthreads();
    __threadfence();

    // clean_key[row] from compacted winners (one-hot in practice)
    int m = g_nwin;
    const float F = (float)(6.283185307179586 / 4096.0);  // fl(2*pi/W)
    float fw = (float)row;
    float ckre = 0.f, ckim = 0.f;
    for (int i = 0; i < m; i++) {
        int   n = g_winn[i];
        float a = g_wina[i];
        float freq = (float)(n + 1) * F;   // reference rounding order
        float ph   = freq * fw;
        float sn, cs;
        sincosf(ph, &sn, &cs);
        ckre = fmaf(a, cs, ckre);
        ckim = fmaf(a, sn, ckim);
    }

    // stream: load (L2-prefetched) row, multiply, store
#pragma unroll
    for (int k = 0; k < 4; k++) {
        int i = i0 + k * 256;
        float4 a = hr[i], b = hi[i];
        float4 o0, o1;
        o0.x = a.x * ckre - b.x * ckim;  o1.x = a.x * ckim + b.x * ckre;
        o0.y = a.y * ckre - b.y * ckim;  o1.y = a.y * ckim + b.y * ckre;
        o0.z = a.z * ckre - b.z * ckim;  o1.z = a.z * ckim + b.z * ckre;
        o0.w = a.w * ckre - b.w * ckim;  o1.w = a.w * ckim + b.w * ckre;
        __stcs(&out[i],          o0);    // real plane (streaming store)
        __stcs(&out[i + W * S4], o1);    // imag plane
    }
}

// ---------------- launcher ----------------
extern "C" void kernel_launch(void* const* d_in, const int* in_sizes, int n_in,
                              void* d_out, int out_size) {
    const float4* hr = (const float4*)d_in[0];
    const float4* hi = (const float4*)d_in[1];
    const float4* cr = (const float4*)d_in[2];
    const float4* ci = (const float4*)d_in[3];
    const int*    nk = (const int*)d_in[4];

    k_mix  <<<W, 256>>>(hr, hi, cr, ci);
    k_fused<<<W, 256>>>(hr, hi, (float4*)d_out, nk);
}